// round 4
// baseline (speedup 1.0000x reference)
#include <cuda_runtime.h>
#include <cstdint>
#include <math.h>

#define DI __device__ __forceinline__

#define NN 256
#define HH 1024
#define EE 512
#define VV 32000
#define KXT 2560
#define PRED_OFF 8192000
#define HC (NN*HH)

__device__ __align__(16) float g_X[NN * KXT];
__device__ __align__(16) float g_gates[4 * NN * 4096];
__device__ __align__(16) float g_h1[NN * HH];

// ---------- helpers ----------
DI uint32_t smem_u32(const void* p) {
    uint32_t a;
    asm("{ .reg .u64 t; cvta.to.shared.u64 t, %1; cvt.u32.u64 %0, t; }" : "=r"(a) : "l"(p));
    return a;
}
DI uint32_t f2tf(float x) {
    uint32_t r;
    asm("cvt.rna.tf32.f32 %0, %1;" : "=r"(r) : "f"(x));
    return r;
}
DI void cpa16(uint32_t s, const void* g) {
    asm volatile("cp.async.cg.shared.global [%0], [%1], 16;" :: "r"(s), "l"(g));
}
DI uint32_t lds_u32(uint32_t a) {
    uint32_t x;
    asm volatile("ld.shared.b32 %0, [%1];" : "=r"(x) : "r"(a));
    return x;
}
DI uint32_t lds_tf32(uint32_t a) {
    float x;
    asm volatile("ld.shared.f32 %0, [%1];" : "=f"(x) : "r"(a));
    return f2tf(x);
}
DI void mma4(float c[4], const uint32_t a[4], const uint32_t b[2]) {
    asm volatile(
        "mma.sync.aligned.m16n8k8.row.col.f32.tf32.tf32.f32 "
        "{%0,%1,%2,%3}, {%4,%5,%6,%7}, {%8,%9}, {%0,%1,%2,%3};"
        : "+f"(c[0]), "+f"(c[1]), "+f"(c[2]), "+f"(c[3])
        : "r"(a[0]), "r"(a[1]), "r"(a[2]), "r"(a[3]), "r"(b[0]), "r"(b[1]));
}

// ---------- B-source functors ----------
struct BFc {
    const float* w;
    DI const float* ptr(int r, int k) const { return w + (size_t)r * HH + k; }
};
struct BGates {
    const float* wih;
    const float* whh;
    DI const float* ptr(int r, int k) const {
        return (k < 1536) ? wih + (size_t)r * 1536 + k
                          : whh + (size_t)r * 1024 + (k - 1536);
    }
};

// ---------- GEMM mainloop: CTA 128x128, warp 64x64, ktile 32 ----------
// smem stage: A[128][36] + B[128][36] floats = 36864 B, 2 stages = 73728 B
#define STAGE_B 36864
#define GEMM_SMEM (2 * STAGE_B)

template <class BS>
DI void load_tiles(uint32_t As, uint32_t Bs, const float* A, int lda, BS bs,
                   int ntb, int kg, int t) {
#pragma unroll
    for (int i = 0; i < 8; i++) {
        int idx = i * 128 + t, r = idx >> 3, c = idx & 7;
        cpa16(As + (uint32_t)(r * 36 + c * 4) * 4, A + (size_t)r * lda + kg + c * 4);
    }
#pragma unroll
    for (int i = 0; i < 8; i++) {
        int idx = i * 128 + t, r = idx >> 3, c = idx & 7;
        cpa16(Bs + (uint32_t)(r * 36 + c * 4) * 4, bs.ptr(ntb + r, kg + c * 4));
    }
}

template <class BS>
DI void gemm_main(float acc[4][8][4], const float* A, int lda, BS bs, int ntb,
                  int k0, int ktiles, uint32_t sbase) {
    const int t = threadIdx.x;
    const int warp = t >> 5, lane = t & 31;
    const int wm = (warp >> 1) * 64, wn = (warp & 1) * 64;
    const int gid = lane >> 2, tid = lane & 3;

#pragma unroll
    for (int mf = 0; mf < 4; mf++)
#pragma unroll
        for (int nf = 0; nf < 8; nf++)
#pragma unroll
            for (int j = 0; j < 4; j++) acc[mf][nf][j] = 0.f;

    load_tiles(sbase, sbase + 18432, A, lda, bs, ntb, k0, t);
    asm volatile("cp.async.commit_group;");

    for (int kt = 0; kt < ktiles; kt++) {
        if (kt + 1 < ktiles) {
            uint32_t st = ((kt + 1) & 1) * STAGE_B;
            load_tiles(sbase + st, sbase + st + 18432, A, lda, bs, ntb,
                       k0 + (kt + 1) * 32, t);
            asm volatile("cp.async.commit_group;");
            asm volatile("cp.async.wait_group 1;");
        } else {
            asm volatile("cp.async.wait_group 0;");
        }
        __syncthreads();

        const uint32_t As = sbase + (kt & 1) * STAGE_B;
        const uint32_t Bs = As + 18432;
#pragma unroll
        for (int ks = 0; ks < 4; ks++) {
            uint32_t a[4][4], b[8][2];
#pragma unroll
            for (int mf = 0; mf < 4; mf++) {
                uint32_t ad = As + (uint32_t)((wm + mf * 16 + gid) * 36 + ks * 8 + tid) * 4;
                a[mf][0] = lds_u32(ad);
                a[mf][1] = lds_u32(ad + 1152);
                a[mf][2] = lds_u32(ad + 16);
                a[mf][3] = lds_u32(ad + 1168);
            }
#pragma unroll
            for (int nf = 0; nf < 8; nf++) {
                uint32_t bd = Bs + (uint32_t)((wn + nf * 8 + gid) * 36 + ks * 8 + tid) * 4;
                b[nf][0] = lds_tf32(bd);
                b[nf][1] = lds_tf32(bd + 16);
            }
#pragma unroll
            for (int mf = 0; mf < 4; mf++)
#pragma unroll
                for (int nf = 0; nf < 8; nf++) mma4(acc[mf][nf], a[mf], b[nf]);
        }
        __syncthreads();
    }
}

// ---------- Kernel 1: fused attention + X staging ----------
__global__ void __launch_bounds__(256) attn_kernel(
    const int* __restrict__ input, const float* __restrict__ enc,
    const float* __restrict__ hidden, const float* __restrict__ emb,
    const float* __restrict__ W_energy, const float* __restrict__ b_energy)
{
    __shared__ __align__(16) float w2s[1024];
    __shared__ __align__(16) float m_acc[8][1024];
    __shared__ float red[8];
    __shared__ float s_an;
    __shared__ float m_ml[8][2];

    const int n = blockIdx.x, t = threadIdx.x;
    const int lane = t & 31, w = t >> 5;
    const float* wrow = W_energy + (size_t)1023 * 2048;
    const float* h0 = hidden + (size_t)n * HH;

    ((float4*)w2s)[t] = ((const float4*)(wrow + 1024))[t];

    float4 ha = ((const float4*)h0)[t];
    {
        float4 wa = ((const float4*)wrow)[t];
        float part = ha.x * wa.x + ha.y * wa.y + ha.z * wa.z + ha.w * wa.w;
#pragma unroll
        for (int o = 16; o > 0; o >>= 1) part += __shfl_xor_sync(0xffffffffu, part, o);
        if (lane == 0) red[w] = part;
    }
    // stage emb + h0 (pre-rounded tf32) into X
    {
        int vix = input[n];
        if (t < 128) {
            float4 e4 = ((const float4*)(emb + (size_t)vix * EE))[t];
            uint4 u = make_uint4(f2tf(e4.x), f2tf(e4.y), f2tf(e4.z), f2tf(e4.w));
            ((uint4*)(g_X + (size_t)n * KXT + 1024))[t] = u;
        }
        uint4 u = make_uint4(f2tf(ha.x), f2tf(ha.y), f2tf(ha.z), f2tf(ha.w));
        ((uint4*)(g_X + (size_t)n * KXT + 1536))[t] = u;
    }
    __syncthreads();
    if (t == 0) {
        float s = 0.f;
        for (int i = 0; i < 8; i++) s += red[i];
        s_an = s + b_energy[1023];
    }
    __syncthreads();
    const float a_n = s_an;

    // per-warp online softmax over s = w, w+8, ..., w+120 (sync-free loop)
    float4 wv[8];
#pragma unroll
    for (int i = 0; i < 8; i++) wv[i] = ((const float4*)w2s)[lane * 8 + i];

    const float4* base = (const float4*)enc + (size_t)w * 65536 + n * 256 + lane * 8;
    float4 v[8];
#pragma unroll
    for (int i = 0; i < 8; i++) v[i] = base[i];

    float m = -1e30f, l = 0.f;
    float4 acc[8];
#pragma unroll
    for (int i = 0; i < 8; i++) acc[i] = make_float4(0.f, 0.f, 0.f, 0.f);

    for (int si = 0; si < 16; si++) {
        float4 nv[8];
        if (si < 15) {
            const float4* nb = base + (size_t)(si + 1) * 8 * 65536;
#pragma unroll
            for (int i = 0; i < 8; i++) nv[i] = nb[i];
        }
        float d = 0.f;
#pragma unroll
        for (int i = 0; i < 8; i++)
            d += v[i].x * wv[i].x + v[i].y * wv[i].y + v[i].z * wv[i].z + v[i].w * wv[i].w;
#pragma unroll
        for (int o = 16; o > 0; o >>= 1) d += __shfl_xor_sync(0xffffffffu, d, o);
        float e = fmaxf(d + a_n, 0.f);
        float mn = fmaxf(m, e);
        float sc = __expf(m - mn), pw = __expf(e - mn);
        l = l * sc + pw;
#pragma unroll
        for (int i = 0; i < 8; i++) {
            acc[i].x = acc[i].x * sc + pw * v[i].x;
            acc[i].y = acc[i].y * sc + pw * v[i].y;
            acc[i].z = acc[i].z * sc + pw * v[i].z;
            acc[i].w = acc[i].w * sc + pw * v[i].w;
        }
        m = mn;
        if (si < 15) {
#pragma unroll
            for (int i = 0; i < 8; i++) v[i] = nv[i];
        }
    }
    // merge 8 warps
#pragma unroll
    for (int i = 0; i < 8; i++) ((float4*)&m_acc[w][lane * 32])[i] = acc[i];
    if (lane == 0) { m_ml[w][0] = m; m_ml[w][1] = l; }
    __syncthreads();

    {
        float M = -1e30f;
#pragma unroll
        for (int j = 0; j < 8; j++) M = fmaxf(M, m_ml[j][0]);
        float L = 0.f;
        float wj[8];
#pragma unroll
        for (int j = 0; j < 8; j++) {
            wj[j] = __expf(m_ml[j][0] - M);
            L += wj[j] * m_ml[j][1];
        }
        float inv = 1.f / L;
        float4 c = make_float4(0.f, 0.f, 0.f, 0.f);
#pragma unroll
        for (int j = 0; j < 8; j++) {
            float4 aj = ((float4*)&m_acc[j][0])[t];
            c.x += wj[j] * aj.x; c.y += wj[j] * aj.y;
            c.z += wj[j] * aj.z; c.w += wj[j] * aj.w;
        }
        uint4 u = make_uint4(f2tf(c.x * inv), f2tf(c.y * inv), f2tf(c.z * inv), f2tf(c.w * inv));
        ((uint4*)(g_X + (size_t)n * KXT))[t] = u;
    }
}

// ---------- Kernel 2: gates GEMM, split-K=4 ----------
__global__ void __launch_bounds__(128) gates_kernel(
    const float* __restrict__ W_ih, const float* __restrict__ W_hh)
{
    extern __shared__ __align__(16) unsigned char dynsm[];
    const int nt = blockIdx.x, mtile = blockIdx.y, sp = blockIdx.z;
    BGates bs{W_ih, W_hh};
    float acc[4][8][4];
    gemm_main(acc, g_X + (size_t)mtile * 128 * KXT, KXT, bs, nt * 128,
              sp * 640, 20, smem_u32(dynsm));

    const int t = threadIdx.x, warp = t >> 5, lane = t & 31;
    const int wm = (warp >> 1) * 64, wn = (warp & 1) * 64;
    const int gid = lane >> 2, tid = lane & 3;
    float* gbase = g_gates + (size_t)sp * NN * 4096;
#pragma unroll
    for (int mf = 0; mf < 4; mf++) {
        int row = mtile * 128 + wm + mf * 16 + gid;
#pragma unroll
        for (int nf = 0; nf < 8; nf++) {
            int col = nt * 128 + wn + nf * 8 + 2 * tid;
            *(float2*)(gbase + (size_t)row * 4096 + col) =
                make_float2(acc[mf][nf][0], acc[mf][nf][1]);
            *(float2*)(gbase + (size_t)(row + 8) * 4096 + col) =
                make_float2(acc[mf][nf][2], acc[mf][nf][3]);
        }
    }
}

// ---------- Kernel 3: LSTM elementwise ----------
__global__ void __launch_bounds__(256) lstm_kernel(
    const float* __restrict__ cell, const float* __restrict__ b_ih,
    const float* __restrict__ b_hh, float* __restrict__ out)
{
    const int idx = blockIdx.x * 256 + threadIdx.x;
    const int h = idx & 1023;
    const size_t base = (size_t)(idx >> 10) * 4096;
    float gi = 0.f, gf = 0.f, gg = 0.f, go = 0.f;
#pragma unroll
    for (int sp = 0; sp < 4; sp++) {
        const float* g = g_gates + (size_t)sp * NN * 4096 + base;
        gi += g[h]; gf += g[1024 + h]; gg += g[2048 + h]; go += g[3072 + h];
    }
    gi += b_ih[h] + b_hh[h];
    gf += b_ih[1024 + h] + b_hh[1024 + h];
    gg += b_ih[2048 + h] + b_hh[2048 + h];
    go += b_ih[3072 + h] + b_hh[3072 + h];
    float c0 = cell[idx];
    float si = 1.f / (1.f + __expf(-gi));
    float sf = 1.f / (1.f + __expf(-gf));
    float so = 1.f / (1.f + __expf(-go));
    float c1 = sf * c0 + si * tanhf(gg);
    float h1 = so * tanhf(c1);
    ((uint32_t*)g_h1)[idx] = f2tf(h1);   // pre-rounded copy for FC GEMM
    out[PRED_OFF + idx] = h1;            // exact fp32 outputs
    out[PRED_OFF + HC + idx] = c1;
}

// ---------- Kernel 4: FC GEMM ----------
__global__ void __launch_bounds__(128) fc_kernel(
    const float* __restrict__ W_fc, const float* __restrict__ b_fc,
    float* __restrict__ out)
{
    extern __shared__ __align__(16) unsigned char dynsm[];
    const int nt = blockIdx.x, mtile = blockIdx.y;
    BFc bs{W_fc};
    float acc[4][8][4];
    gemm_main(acc, g_h1 + (size_t)mtile * 128 * HH, HH, bs, nt * 128, 0, 32,
              smem_u32(dynsm));

    const int t = threadIdx.x, warp = t >> 5, lane = t & 31;
    const int wm = (warp >> 1) * 64, wn = (warp & 1) * 64;
    const int gid = lane >> 2, tid = lane & 3;
#pragma unroll
    for (int mf = 0; mf < 4; mf++) {
        int row = mtile * 128 + wm + mf * 16 + gid;
#pragma unroll
        for (int nf = 0; nf < 8; nf++) {
            int col = nt * 128 + wn + nf * 8 + 2 * tid;
            float b0 = __ldg(b_fc + col), b1 = __ldg(b_fc + col + 1);
            *(float2*)(out + (size_t)row * VV + col) =
                make_float2(acc[mf][nf][0] + b0, acc[mf][nf][1] + b1);
            *(float2*)(out + (size_t)(row + 8) * VV + col) =
                make_float2(acc[mf][nf][2] + b0, acc[mf][nf][3] + b1);
        }
    }
}

// ---------- launch ----------
extern "C" void kernel_launch(void* const* d_in, const int* in_sizes, int n_in,
                              void* d_out, int out_size) {
    const int*   input    = (const int*)d_in[0];
    const float* enc      = (const float*)d_in[1];
    const float* hidden   = (const float*)d_in[2];
    const float* cell     = (const float*)d_in[3];
    const float* emb      = (const float*)d_in[4];
    const float* W_energy = (const float*)d_in[5];
    const float* b_energy = (const float*)d_in[6];
    const float* W_ih     = (const float*)d_in[7];
    const float* b_ih     = (const float*)d_in[8];
    const float* W_hh     = (const float*)d_in[9];
    const float* b_hh     = (const float*)d_in[10];
    const float* W_fc     = (const float*)d_in[11];
    const float* b_fc     = (const float*)d_in[12];
    float* out = (float*)d_out;

    cudaFuncSetAttribute(gates_kernel, cudaFuncAttributeMaxDynamicSharedMemorySize, GEMM_SMEM);
    cudaFuncSetAttribute(fc_kernel, cudaFuncAttributeMaxDynamicSharedMemorySize, GEMM_SMEM);

    attn_kernel<<<256, 256>>>(input, enc, hidden, emb, W_energy, b_energy);
    gates_kernel<<<dim3(32, 2, 4), 128, GEMM_SMEM>>>(W_ih, W_hh);
    lstm_kernel<<<1024, 256>>>(cell, b_ih, b_hh, out);
    fc_kernel<<<dim3(250, 2), 128, GEMM_SMEM>>>(W_fc, b_fc, out);
}

// round 6
// speedup vs baseline: 1.0759x; 1.0759x over previous
#include <cuda_runtime.h>
#include <cstdint>
#include <math.h>

#define DI __device__ __forceinline__

#define NN 256
#define HH 1024
#define EE 512
#define VV 32000
#define KXT 2560
#define PRED_OFF 8192000
#define HC (NN*HH)

__device__ __align__(16) float g_X[NN * KXT];
__device__ __align__(16) float g_gates[4 * NN * 4096];
__device__ __align__(16) float g_h1[NN * HH];

// ---------- helpers ----------
DI uint32_t smem_u32(const void* p) {
    uint32_t a;
    asm("{ .reg .u64 t; cvta.to.shared.u64 t, %1; cvt.u32.u64 %0, t; }" : "=r"(a) : "l"(p));
    return a;
}
DI uint32_t f2tf(float x) {
    uint32_t r;
    asm("cvt.rna.tf32.f32 %0, %1;" : "=r"(r) : "f"(x));
    return r;
}
DI void cpa16(uint32_t s, const void* g) {
    asm volatile("cp.async.cg.shared.global [%0], [%1], 16;" :: "r"(s), "l"(g));
}
DI uint32_t lds_u32(uint32_t a) {
    uint32_t x;
    asm volatile("ld.shared.b32 %0, [%1];" : "=r"(x) : "r"(a));
    return x;
}
DI uint32_t lds_tf32(uint32_t a) {
    float x;
    asm volatile("ld.shared.f32 %0, [%1];" : "=f"(x) : "r"(a));
    return f2tf(x);
}
DI void mma4(float c[4], const uint32_t a[4], const uint32_t b[2]) {
    asm volatile(
        "mma.sync.aligned.m16n8k8.row.col.f32.tf32.tf32.f32 "
        "{%0,%1,%2,%3}, {%4,%5,%6,%7}, {%8,%9}, {%0,%1,%2,%3};"
        : "+f"(c[0]), "+f"(c[1]), "+f"(c[2]), "+f"(c[3])
        : "r"(a[0]), "r"(a[1]), "r"(a[2]), "r"(a[3]), "r"(b[0]), "r"(b[1]));
}

// ---------- B-source functors ----------
struct BFc {
    const float* w;
    DI const float* ptr(int r, int k) const { return w + (size_t)r * HH + k; }
};
struct BGates {
    const float* wih;
    const float* whh;
    DI const float* ptr(int r, int k) const {
        return (k < 1536) ? wih + (size_t)r * 1536 + k
                          : whh + (size_t)r * 1024 + (k - 1536);
    }
};

// ---------- GEMM: CTA tile 256x128, 8 warps of 64x64, ktile 32 ----------
// smem rows: 32 floats (128B), element k of row r in 16B-chunk ((k>>2) ^ (r&7)).
// A stage: 256*128B = 32768, B stage: 128*128B = 16384
#define STAGE_B 49152
#define GEMM_SMEM (2 * STAGE_B)

template <class BS>
DI void load_tiles(uint32_t As, uint32_t Bs, const float* A, int lda, BS bs,
                   int ntb, int kg, int t) {
#pragma unroll
    for (int i = 0; i < 8; i++) {  // A: 256 rows x 8 chunks
        int idx = i * 256 + t, r = idx >> 3, c = idx & 7;
        cpa16(As + (uint32_t)(r * 128 + ((c ^ (r & 7)) << 4)),
              A + (size_t)r * lda + kg + c * 4);
    }
#pragma unroll
    for (int i = 0; i < 4; i++) {  // B: 128 rows x 8 chunks
        int idx = i * 256 + t, r = idx >> 3, c = idx & 7;
        cpa16(Bs + (uint32_t)(r * 128 + ((c ^ (r & 7)) << 4)),
              bs.ptr(ntb + r, kg + c * 4));
    }
}

template <class BS>
DI void gemm_main(float acc[4][8][4], const float* A, int lda, BS bs, int ntb,
                  int k0, int ktiles, uint32_t sbase) {
    const int t = threadIdx.x;  // 256
    const int warp = t >> 5, lane = t & 31;
    const int wm = (warp >> 1) * 64, wn = (warp & 1) * 64;
    const int gid = lane >> 2, tid = lane & 3;

#pragma unroll
    for (int mf = 0; mf < 4; mf++)
#pragma unroll
        for (int nf = 0; nf < 8; nf++)
#pragma unroll
            for (int j = 0; j < 4; j++) acc[mf][nf][j] = 0.f;

    load_tiles(sbase, sbase + 32768, A, lda, bs, ntb, k0, t);
    asm volatile("cp.async.commit_group;");

    for (int kt = 0; kt < ktiles; kt++) {
        if (kt + 1 < ktiles) {
            uint32_t st = ((kt + 1) & 1) * STAGE_B;
            load_tiles(sbase + st, sbase + st + 32768, A, lda, bs, ntb,
                       k0 + (kt + 1) * 32, t);
            asm volatile("cp.async.commit_group;");
            asm volatile("cp.async.wait_group 1;");
        } else {
            asm volatile("cp.async.wait_group 0;");
        }
        __syncthreads();

        const uint32_t As = sbase + (kt & 1) * STAGE_B;
        const uint32_t Bs = As + 32768;
#pragma unroll
        for (int ks = 0; ks < 4; ks++) {
            const uint32_t c0 = (uint32_t)((((2 * ks) ^ gid) << 4) + tid * 4);
            const uint32_t c1 = (uint32_t)((((2 * ks + 1) ^ gid) << 4) + tid * 4);
            uint32_t a[4][4], b[8][2];
#pragma unroll
            for (int mf = 0; mf < 4; mf++) {
                uint32_t ro = As + (uint32_t)((wm + mf * 16 + gid) * 128);
                a[mf][0] = lds_u32(ro + c0);
                a[mf][1] = lds_u32(ro + c0 + 1024);
                a[mf][2] = lds_u32(ro + c1);
                a[mf][3] = lds_u32(ro + c1 + 1024);
            }
#pragma unroll
            for (int nf = 0; nf < 8; nf++) {
                uint32_t ro = Bs + (uint32_t)((wn + nf * 8 + gid) * 128);
                b[nf][0] = lds_tf32(ro + c0);
                b[nf][1] = lds_tf32(ro + c1);
            }
#pragma unroll
            for (int mf = 0; mf < 4; mf++)
#pragma unroll
                for (int nf = 0; nf < 8; nf++) mma4(acc[mf][nf], a[mf], b[nf]);
        }
        __syncthreads();
    }
}

// ---------- Kernel 1: fused attention + X staging ----------
__global__ void __launch_bounds__(256) attn_kernel(
    const int* __restrict__ input, const float* __restrict__ enc,
    const float* __restrict__ hidden, const float* __restrict__ emb,
    const float* __restrict__ W_energy, const float* __restrict__ b_energy)
{
    __shared__ __align__(16) float w2s[1024];
    __shared__ __align__(16) float m_acc[8][1024];
    __shared__ float red[8];
    __shared__ float s_an;
    __shared__ float m_ml[8][2];

    const int n = blockIdx.x, t = threadIdx.x;
    const int lane = t & 31, w = t >> 5;
    const float* wrow = W_energy + (size_t)1023 * 2048;
    const float* h0 = hidden + (size_t)n * HH;

    ((float4*)w2s)[t] = ((const float4*)(wrow + 1024))[t];

    float4 ha = ((const float4*)h0)[t];
    {
        float4 wa = ((const float4*)wrow)[t];
        float part = ha.x * wa.x + ha.y * wa.y + ha.z * wa.z + ha.w * wa.w;
#pragma unroll
        for (int o = 16; o > 0; o >>= 1) part += __shfl_xor_sync(0xffffffffu, part, o);
        if (lane == 0) red[w] = part;
    }
    {
        int vix = input[n];
        if (t < 128) {
            float4 e4 = ((const float4*)(emb + (size_t)vix * EE))[t];
            uint4 u = make_uint4(f2tf(e4.x), f2tf(e4.y), f2tf(e4.z), f2tf(e4.w));
            ((uint4*)(g_X + (size_t)n * KXT + 1024))[t] = u;
        }
        uint4 u = make_uint4(f2tf(ha.x), f2tf(ha.y), f2tf(ha.z), f2tf(ha.w));
        ((uint4*)(g_X + (size_t)n * KXT + 1536))[t] = u;
    }
    __syncthreads();
    if (t == 0) {
        float s = 0.f;
        for (int i = 0; i < 8; i++) s += red[i];
        s_an = s + b_energy[1023];
    }
    __syncthreads();
    const float a_n = s_an;

    // per-warp online softmax over s = w, w+8, ..., w+120; coalesced lane loads
    float4 wv[8];
#pragma unroll
    for (int i = 0; i < 8; i++) wv[i] = ((const float4*)w2s)[i * 32 + lane];

    const float4* base = (const float4*)enc + (size_t)w * 65536 + n * 256 + lane;
    float4 v[8];
#pragma unroll
    for (int i = 0; i < 8; i++) v[i] = base[i * 32];

    float m = -1e30f, l = 0.f;
    float4 acc[8];
#pragma unroll
    for (int i = 0; i < 8; i++) acc[i] = make_float4(0.f, 0.f, 0.f, 0.f);

    for (int si = 0; si < 16; si++) {
        float4 nv[8];
        if (si < 15) {
            const float4* nb = base + (size_t)(si + 1) * 8 * 65536;
#pragma unroll
            for (int i = 0; i < 8; i++) nv[i] = nb[i * 32];
        }
        float d = 0.f;
#pragma unroll
        for (int i = 0; i < 8; i++)
            d += v[i].x * wv[i].x + v[i].y * wv[i].y + v[i].z * wv[i].z + v[i].w * wv[i].w;
#pragma unroll
        for (int o = 16; o > 0; o >>= 1) d += __shfl_xor_sync(0xffffffffu, d, o);
        float e = fmaxf(d + a_n, 0.f);
        float mn = fmaxf(m, e);
        float sc = __expf(m - mn), pw = __expf(e - mn);
        l = l * sc + pw;
#pragma unroll
        for (int i = 0; i < 8; i++) {
            acc[i].x = acc[i].x * sc + pw * v[i].x;
            acc[i].y = acc[i].y * sc + pw * v[i].y;
            acc[i].z = acc[i].z * sc + pw * v[i].z;
            acc[i].w = acc[i].w * sc + pw * v[i].w;
        }
        m = mn;
        if (si < 15) {
#pragma unroll
            for (int i = 0; i < 8; i++) v[i] = nv[i];
        }
    }
#pragma unroll
    for (int i = 0; i < 8; i++) ((float4*)&m_acc[w][0])[i * 32 + lane] = acc[i];
    if (lane == 0) { m_ml[w][0] = m; m_ml[w][1] = l; }
    __syncthreads();

    {
        float M = -1e30f;
#pragma unroll
        for (int j = 0; j < 8; j++) M = fmaxf(M, m_ml[j][0]);
        float L = 0.f;
        float wj[8];
#pragma unroll
        for (int j = 0; j < 8; j++) {
            wj[j] = __expf(m_ml[j][0] - M);
            L += wj[j] * m_ml[j][1];
        }
        float inv = 1.f / L;
        float4 c = make_float4(0.f, 0.f, 0.f, 0.f);
#pragma unroll
        for (int j = 0; j < 8; j++) {
            float4 aj = ((float4*)&m_acc[j][0])[t];
            c.x += wj[j] * aj.x; c.y += wj[j] * aj.y;
            c.z += wj[j] * aj.z; c.w += wj[j] * aj.w;
        }
        uint4 u = make_uint4(f2tf(c.x * inv), f2tf(c.y * inv), f2tf(c.z * inv), f2tf(c.w * inv));
        ((uint4*)(g_X + (size_t)n * KXT))[t] = u;
    }
}

// ---------- Kernel 2: gates GEMM, tile 256x128, split-K=4 ----------
__global__ void __launch_bounds__(256) gates_kernel(
    const float* __restrict__ W_ih, const float* __restrict__ W_hh)
{
    extern __shared__ __align__(16) unsigned char dynsm[];
    const int nt = blockIdx.x, sp = blockIdx.y;
    BGates bs{W_ih, W_hh};
    float acc[4][8][4];
    gemm_main(acc, g_X, KXT, bs, nt * 128, sp * 640, 20, smem_u32(dynsm));

    const int t = threadIdx.x, warp = t >> 5, lane = t & 31;
    const int wm = (warp >> 1) * 64, wn = (warp & 1) * 64;
    const int gid = lane >> 2, tid = lane & 3;
    float* gbase = g_gates + (size_t)sp * NN * 4096;
#pragma unroll
    for (int mf = 0; mf < 4; mf++) {
        int row = wm + mf * 16 + gid;
#pragma unroll
        for (int nf = 0; nf < 8; nf++) {
            int col = nt * 128 + wn + nf * 8 + 2 * tid;
            *(float2*)(gbase + (size_t)row * 4096 + col) =
                make_float2(acc[mf][nf][0], acc[mf][nf][1]);
            *(float2*)(gbase + (size_t)(row + 8) * 4096 + col) =
                make_float2(acc[mf][nf][2], acc[mf][nf][3]);
        }
    }
}

// ---------- Kernel 3: LSTM elementwise ----------
__global__ void __launch_bounds__(256) lstm_kernel(
    const float* __restrict__ cell, const float* __restrict__ b_ih,
    const float* __restrict__ b_hh, float* __restrict__ out)
{
    const int idx = blockIdx.x * 256 + threadIdx.x;
    const int h = idx & 1023;
    const size_t base = (size_t)(idx >> 10) * 4096;
    float gi = 0.f, gf = 0.f, gg = 0.f, go = 0.f;
#pragma unroll
    for (int sp = 0; sp < 4; sp++) {
        const float* g = g_gates + (size_t)sp * NN * 4096 + base;
        gi += g[h]; gf += g[1024 + h]; gg += g[2048 + h]; go += g[3072 + h];
    }
    gi += b_ih[h] + b_hh[h];
    gf += b_ih[1024 + h] + b_hh[1024 + h];
    gg += b_ih[2048 + h] + b_hh[2048 + h];
    go += b_ih[3072 + h] + b_hh[3072 + h];
    float c0 = cell[idx];
    float si = 1.f / (1.f + __expf(-gi));
    float sf = 1.f / (1.f + __expf(-gf));
    float so = 1.f / (1.f + __expf(-go));
    float c1 = sf * c0 + si * tanhf(gg);
    float h1 = so * tanhf(c1);
    ((uint32_t*)g_h1)[idx] = f2tf(h1);   // pre-rounded copy for FC GEMM
    out[PRED_OFF + idx] = h1;            // exact fp32 outputs
    out[PRED_OFF + HC + idx] = c1;
}

// ---------- Kernel 4: FC GEMM, tile 256x128 (single W_fc pass) ----------
__global__ void __launch_bounds__(256) fc_kernel(
    const float* __restrict__ W_fc, const float* __restrict__ b_fc,
    float* __restrict__ out)
{
    extern __shared__ __align__(16) unsigned char dynsm[];
    const int nt = blockIdx.x;
    BFc bs{W_fc};
    float acc[4][8][4];
    gemm_main(acc, g_h1, HH, bs, nt * 128, 0, 32, smem_u32(dynsm));

    const int t = threadIdx.x, warp = t >> 5, lane = t & 31;
    const int wm = (warp >> 1) * 64, wn = (warp & 1) * 64;
    const int gid = lane >> 2, tid = lane & 3;
#pragma unroll
    for (int mf = 0; mf < 4; mf++) {
        int row = wm + mf * 16 + gid;
#pragma unroll
        for (int nf = 0; nf < 8; nf++) {
            int col = nt * 128 + wn + nf * 8 + 2 * tid;
            float b0 = __ldg(b_fc + col), b1 = __ldg(b_fc + col + 1);
            *(float2*)(out + (size_t)row * VV + col) =
                make_float2(acc[mf][nf][0] + b0, acc[mf][nf][1] + b1);
            *(float2*)(out + (size_t)(row + 8) * VV + col) =
                make_float2(acc[mf][nf][2] + b0, acc[mf][nf][3] + b1);
        }
    }
}

// ---------- launch ----------
extern "C" void kernel_launch(void* const* d_in, const int* in_sizes, int n_in,
                              void* d_out, int out_size) {
    const int*   input    = (const int*)d_in[0];
    const float* enc      = (const float*)d_in[1];
    const float* hidden   = (const float*)d_in[2];
    const float* cell     = (const float*)d_in[3];
    const float* emb      = (const float*)d_in[4];
    const float* W_energy = (const float*)d_in[5];
    const float* b_energy = (const float*)d_in[6];
    const float* W_ih     = (const float*)d_in[7];
    const float* b_ih     = (const float*)d_in[8];
    const float* W_hh     = (const float*)d_in[9];
    const float* b_hh     = (const float*)d_in[10];
    const float* W_fc     = (const float*)d_in[11];
    const float* b_fc     = (const float*)d_in[12];
    float* out = (float*)d_out;

    cudaFuncSetAttribute(gates_kernel, cudaFuncAttributeMaxDynamicSharedMemorySize, GEMM_SMEM);
    cudaFuncSetAttribute(fc_kernel, cudaFuncAttributeMaxDynamicSharedMemorySize, GEMM_SMEM);

    attn_kernel<<<256, 256>>>(input, enc, hidden, emb, W_energy, b_energy);
    gates_kernel<<<dim3(32, 4), 256, GEMM_SMEM>>>(W_ih, W_hh);
    lstm_kernel<<<1024, 256>>>(cell, b_ih, b_hh, out);
    fc_kernel<<<250, 256, GEMM_SMEM>>>(W_fc, b_fc, out);
}

// round 7
// speedup vs baseline: 1.0991x; 1.0215x over previous
#include <cuda_runtime.h>
#include <cstdint>
#include <math.h>

#define DI __device__ __forceinline__

#define NN 256
#define HH 1024
#define EE 512
#define VV 32000
#define KXT 2560
#define PRED_OFF 8192000
#define HC (NN*HH)

__device__ __align__(16) float g_X[NN * KXT];
__device__ __align__(16) float g_gates[4 * NN * 4096];
__device__ __align__(16) float g_h1[NN * HH];

// ---------- helpers ----------
DI uint32_t smem_u32(const void* p) {
    uint32_t a;
    asm("{ .reg .u64 t; cvta.to.shared.u64 t, %1; cvt.u32.u64 %0, t; }" : "=r"(a) : "l"(p));
    return a;
}
DI uint32_t f2tf(float x) {
    uint32_t r;
    asm("cvt.rna.tf32.f32 %0, %1;" : "=r"(r) : "f"(x));
    return r;
}
DI void cpa16(uint32_t s, const void* g) {
    asm volatile("cp.async.cg.shared.global [%0], [%1], 16;" :: "r"(s), "l"(g));
}
DI uint32_t lds_u32(uint32_t a) {
    uint32_t x;
    asm volatile("ld.shared.b32 %0, [%1];" : "=r"(x) : "r"(a));
    return x;
}
DI uint32_t lds_tf32(uint32_t a) {
    float x;
    asm volatile("ld.shared.f32 %0, [%1];" : "=f"(x) : "r"(a));
    return f2tf(x);
}
DI void mma4(float c[4], const uint32_t a[4], const uint32_t b[2]) {
    asm volatile(
        "mma.sync.aligned.m16n8k8.row.col.f32.tf32.tf32.f32 "
        "{%0,%1,%2,%3}, {%4,%5,%6,%7}, {%8,%9}, {%0,%1,%2,%3};"
        : "+f"(c[0]), "+f"(c[1]), "+f"(c[2]), "+f"(c[3])
        : "r"(a[0]), "r"(a[1]), "r"(a[2]), "r"(a[3]), "r"(b[0]), "r"(b[1]));
}

// ---------- B-source functors ----------
struct BFc {
    const float* w;
    DI const float* ptr(int r, int k) const { return w + (size_t)r * HH + k; }
};
struct BGates {
    const float* wih;
    const float* whh;
    DI const float* ptr(int r, int k) const {
        return (k < 1536) ? wih + (size_t)r * 1536 + k
                          : whh + (size_t)r * 1024 + (k - 1536);
    }
};

// ---------- GEMM: CTA tile 256x128, 512 thr = 16 warps of 64x32, ktile 32 ----------
// smem rows: 32 floats (128B), element k of row r in 16B-chunk ((k>>2) ^ (r&7)).
// A stage: 256*128B = 32768, B stage: 128*128B = 16384
#define STAGE_B 49152
#define GEMM_SMEM (2 * STAGE_B)

template <class BS>
DI void load_tiles(uint32_t As, uint32_t Bs, const float* A, int lda, BS bs,
                   int ntb, int kg, int t) {
#pragma unroll
    for (int i = 0; i < 4; i++) {  // A: 256 rows x 8 chunks = 2048
        int idx = i * 512 + t, r = idx >> 3, c = idx & 7;
        cpa16(As + (uint32_t)(r * 128 + ((c ^ (r & 7)) << 4)),
              A + (size_t)r * lda + kg + c * 4);
    }
#pragma unroll
    for (int i = 0; i < 2; i++) {  // B: 128 rows x 8 chunks = 1024
        int idx = i * 512 + t, r = idx >> 3, c = idx & 7;
        cpa16(Bs + (uint32_t)(r * 128 + ((c ^ (r & 7)) << 4)),
              bs.ptr(ntb + r, kg + c * 4));
    }
}

template <class BS>
DI void gemm_main(float acc[4][4][4], const float* A, int lda, BS bs, int ntb,
                  int k0, int ktiles, uint32_t sbase) {
    const int t = threadIdx.x;  // 512
    const int warp = t >> 5, lane = t & 31;
    const int wm = (warp >> 2) * 64, wn = (warp & 3) * 32;
    const int gid = lane >> 2, tid = lane & 3;

#pragma unroll
    for (int mf = 0; mf < 4; mf++)
#pragma unroll
        for (int nf = 0; nf < 4; nf++)
#pragma unroll
            for (int j = 0; j < 4; j++) acc[mf][nf][j] = 0.f;

    load_tiles(sbase, sbase + 32768, A, lda, bs, ntb, k0, t);
    asm volatile("cp.async.commit_group;");

    for (int kt = 0; kt < ktiles; kt++) {
        if (kt + 1 < ktiles) {
            uint32_t st = ((kt + 1) & 1) * STAGE_B;
            load_tiles(sbase + st, sbase + st + 32768, A, lda, bs, ntb,
                       k0 + (kt + 1) * 32, t);
            asm volatile("cp.async.commit_group;");
            asm volatile("cp.async.wait_group 1;");
        } else {
            asm volatile("cp.async.wait_group 0;");
        }
        __syncthreads();

        const uint32_t As = sbase + (kt & 1) * STAGE_B;
        const uint32_t Bs = As + 32768;
#pragma unroll
        for (int ks = 0; ks < 4; ks++) {
            const uint32_t c0 = (uint32_t)((((2 * ks) ^ gid) << 4) + tid * 4);
            const uint32_t c1 = (uint32_t)((((2 * ks + 1) ^ gid) << 4) + tid * 4);
            uint32_t a[4][4], b[4][2];
#pragma unroll
            for (int mf = 0; mf < 4; mf++) {
                uint32_t ro = As + (uint32_t)((wm + mf * 16 + gid) * 128);
                a[mf][0] = lds_u32(ro + c0);
                a[mf][1] = lds_u32(ro + c0 + 1024);
                a[mf][2] = lds_u32(ro + c1);
                a[mf][3] = lds_u32(ro + c1 + 1024);
            }
#pragma unroll
            for (int nf = 0; nf < 4; nf++) {
                uint32_t ro = Bs + (uint32_t)((wn + nf * 8 + gid) * 128);
                b[nf][0] = lds_tf32(ro + c0);
                b[nf][1] = lds_tf32(ro + c1);
            }
#pragma unroll
            for (int mf = 0; mf < 4; mf++)
#pragma unroll
                for (int nf = 0; nf < 4; nf++) mma4(acc[mf][nf], a[mf], b[nf]);
        }
        __syncthreads();
    }
}

// ---------- Kernel 1: fused attention + X staging ----------
__global__ void __launch_bounds__(256) attn_kernel(
    const int* __restrict__ input, const float* __restrict__ enc,
    const float* __restrict__ hidden, const float* __restrict__ emb,
    const float* __restrict__ W_energy, const float* __restrict__ b_energy)
{
    __shared__ __align__(16) float w2s[1024];
    __shared__ __align__(16) float m_acc[8][1024];
    __shared__ float red[8];
    __shared__ float s_an;
    __shared__ float m_ml[8][2];

    const int n = blockIdx.x, t = threadIdx.x;
    const int lane = t & 31, w = t >> 5;
    const float* wrow = W_energy + (size_t)1023 * 2048;
    const float* h0 = hidden + (size_t)n * HH;

    ((float4*)w2s)[t] = ((const float4*)(wrow + 1024))[t];

    float4 ha = ((const float4*)h0)[t];
    {
        float4 wa = ((const float4*)wrow)[t];
        float part = ha.x * wa.x + ha.y * wa.y + ha.z * wa.z + ha.w * wa.w;
#pragma unroll
        for (int o = 16; o > 0; o >>= 1) part += __shfl_xor_sync(0xffffffffu, part, o);
        if (lane == 0) red[w] = part;
    }
    {
        int vix = input[n];
        if (t < 128) {
            float4 e4 = ((const float4*)(emb + (size_t)vix * EE))[t];
            uint4 u = make_uint4(f2tf(e4.x), f2tf(e4.y), f2tf(e4.z), f2tf(e4.w));
            ((uint4*)(g_X + (size_t)n * KXT + 1024))[t] = u;
        }
        uint4 u = make_uint4(f2tf(ha.x), f2tf(ha.y), f2tf(ha.z), f2tf(ha.w));
        ((uint4*)(g_X + (size_t)n * KXT + 1536))[t] = u;
    }
    __syncthreads();
    if (t == 0) {
        float s = 0.f;
        for (int i = 0; i < 8; i++) s += red[i];
        s_an = s + b_energy[1023];
    }
    __syncthreads();
    const float a_n = s_an;

    // per-warp online softmax over s = w, w+8, ..., w+120; coalesced lane loads
    float4 wv[8];
#pragma unroll
    for (int i = 0; i < 8; i++) wv[i] = ((const float4*)w2s)[i * 32 + lane];

    const float4* base = (const float4*)enc + (size_t)w * 65536 + n * 256 + lane;
    float4 v[8];
#pragma unroll
    for (int i = 0; i < 8; i++) v[i] = base[i * 32];

    float m = -1e30f, l = 0.f;
    float4 acc[8];
#pragma unroll
    for (int i = 0; i < 8; i++) acc[i] = make_float4(0.f, 0.f, 0.f, 0.f);

    for (int si = 0; si < 16; si++) {
        float4 nv[8];
        if (si < 15) {
            const float4* nb = base + (size_t)(si + 1) * 8 * 65536;
#pragma unroll
            for (int i = 0; i < 8; i++) nv[i] = nb[i * 32];
        }
        float d = 0.f;
#pragma unroll
        for (int i = 0; i < 8; i++)
            d += v[i].x * wv[i].x + v[i].y * wv[i].y + v[i].z * wv[i].z + v[i].w * wv[i].w;
#pragma unroll
        for (int o = 16; o > 0; o >>= 1) d += __shfl_xor_sync(0xffffffffu, d, o);
        float e = fmaxf(d + a_n, 0.f);
        float mn = fmaxf(m, e);
        float sc = __expf(m - mn), pw = __expf(e - mn);
        l = l * sc + pw;
#pragma unroll
        for (int i = 0; i < 8; i++) {
            acc[i].x = acc[i].x * sc + pw * v[i].x;
            acc[i].y = acc[i].y * sc + pw * v[i].y;
            acc[i].z = acc[i].z * sc + pw * v[i].z;
            acc[i].w = acc[i].w * sc + pw * v[i].w;
        }
        m = mn;
        if (si < 15) {
#pragma unroll
            for (int i = 0; i < 8; i++) v[i] = nv[i];
        }
    }
#pragma unroll
    for (int i = 0; i < 8; i++) ((float4*)&m_acc[w][0])[i * 32 + lane] = acc[i];
    if (lane == 0) { m_ml[w][0] = m; m_ml[w][1] = l; }
    __syncthreads();

    {
        float M = -1e30f;
#pragma unroll
        for (int j = 0; j < 8; j++) M = fmaxf(M, m_ml[j][0]);
        float L = 0.f;
        float wj[8];
#pragma unroll
        for (int j = 0; j < 8; j++) {
            wj[j] = __expf(m_ml[j][0] - M);
            L += wj[j] * m_ml[j][1];
        }
        float inv = 1.f / L;
        float4 c = make_float4(0.f, 0.f, 0.f, 0.f);
#pragma unroll
        for (int j = 0; j < 8; j++) {
            float4 aj = ((float4*)&m_acc[j][0])[t];
            c.x += wj[j] * aj.x; c.y += wj[j] * aj.y;
            c.z += wj[j] * aj.z; c.w += wj[j] * aj.w;
        }
        uint4 u = make_uint4(f2tf(c.x * inv), f2tf(c.y * inv), f2tf(c.z * inv), f2tf(c.w * inv));
        ((uint4*)(g_X + (size_t)n * KXT))[t] = u;
    }
}

// ---------- Kernel 2: gates GEMM, tile 256x128, split-K=4 ----------
__global__ void __launch_bounds__(512) gates_kernel(
    const float* __restrict__ W_ih, const float* __restrict__ W_hh)
{
    extern __shared__ __align__(16) unsigned char dynsm[];
    const int nt = blockIdx.x, sp = blockIdx.y;
    BGates bs{W_ih, W_hh};
    float acc[4][4][4];
    gemm_main(acc, g_X, KXT, bs, nt * 128, sp * 640, 20, smem_u32(dynsm));

    const int t = threadIdx.x, warp = t >> 5, lane = t & 31;
    const int wm = (warp >> 2) * 64, wn = (warp & 3) * 32;
    const int gid = lane >> 2, tid = lane & 3;
    float* gbase = g_gates + (size_t)sp * NN * 4096;
#pragma unroll
    for (int mf = 0; mf < 4; mf++) {
        int row = wm + mf * 16 + gid;
#pragma unroll
        for (int nf = 0; nf < 4; nf++) {
            int col = nt * 128 + wn + nf * 8 + 2 * tid;
            *(float2*)(gbase + (size_t)row * 4096 + col) =
                make_float2(acc[mf][nf][0], acc[mf][nf][1]);
            *(float2*)(gbase + (size_t)(row + 8) * 4096 + col) =
                make_float2(acc[mf][nf][2], acc[mf][nf][3]);
        }
    }
}

// ---------- Kernel 3: LSTM elementwise ----------
__global__ void __launch_bounds__(256) lstm_kernel(
    const float* __restrict__ cell, const float* __restrict__ b_ih,
    const float* __restrict__ b_hh, float* __restrict__ out)
{
    const int idx = blockIdx.x * 256 + threadIdx.x;
    const int h = idx & 1023;
    const size_t base = (size_t)(idx >> 10) * 4096;
    float gi = 0.f, gf = 0.f, gg = 0.f, go = 0.f;
#pragma unroll
    for (int sp = 0; sp < 4; sp++) {
        const float* g = g_gates + (size_t)sp * NN * 4096 + base;
        gi += g[h]; gf += g[1024 + h]; gg += g[2048 + h]; go += g[3072 + h];
    }
    gi += b_ih[h] + b_hh[h];
    gf += b_ih[1024 + h] + b_hh[1024 + h];
    gg += b_ih[2048 + h] + b_hh[2048 + h];
    go += b_ih[3072 + h] + b_hh[3072 + h];
    float c0 = cell[idx];
    float si = 1.f / (1.f + __expf(-gi));
    float sf = 1.f / (1.f + __expf(-gf));
    float so = 1.f / (1.f + __expf(-go));
    float c1 = sf * c0 + si * tanhf(gg);
    float h1 = so * tanhf(c1);
    ((uint32_t*)g_h1)[idx] = f2tf(h1);   // pre-rounded copy for FC GEMM
    out[PRED_OFF + idx] = h1;            // exact fp32 outputs
    out[PRED_OFF + HC + idx] = c1;
}

// ---------- Kernel 4: FC GEMM, tile 256x128 (single W_fc pass) ----------
__global__ void __launch_bounds__(512) fc_kernel(
    const float* __restrict__ W_fc, const float* __restrict__ b_fc,
    float* __restrict__ out)
{
    extern __shared__ __align__(16) unsigned char dynsm[];
    const int nt = blockIdx.x;
    BFc bs{W_fc};
    float acc[4][4][4];
    gemm_main(acc, g_h1, HH, bs, nt * 128, 0, 32, smem_u32(dynsm));

    const int t = threadIdx.x, warp = t >> 5, lane = t & 31;
    const int wm = (warp >> 2) * 64, wn = (warp & 3) * 32;
    const int gid = lane >> 2, tid = lane & 3;
#pragma unroll
    for (int mf = 0; mf < 4; mf++) {
        int row = wm + mf * 16 + gid;
#pragma unroll
        for (int nf = 0; nf < 4; nf++) {
            int col = nt * 128 + wn + nf * 8 + 2 * tid;
            float b0 = __ldg(b_fc + col), b1 = __ldg(b_fc + col + 1);
            *(float2*)(out + (size_t)row * VV + col) =
                make_float2(acc[mf][nf][0] + b0, acc[mf][nf][1] + b1);
            *(float2*)(out + (size_t)(row + 8) * VV + col) =
                make_float2(acc[mf][nf][2] + b0, acc[mf][nf][3] + b1);
        }
    }
}

// ---------- launch ----------
extern "C" void kernel_launch(void* const* d_in, const int* in_sizes, int n_in,
                              void* d_out, int out_size) {
    const int*   input    = (const int*)d_in[0];
    const float* enc      = (const float*)d_in[1];
    const float* hidden   = (const float*)d_in[2];
    const float* cell     = (const float*)d_in[3];
    const float* emb      = (const float*)d_in[4];
    const float* W_energy = (const float*)d_in[5];
    const float* b_energy = (const float*)d_in[6];
    const float* W_ih     = (const float*)d_in[7];
    const float* b_ih     = (const float*)d_in[8];
    const float* W_hh     = (const float*)d_in[9];
    const float* b_hh     = (const float*)d_in[10];
    const float* W_fc     = (const float*)d_in[11];
    const float* b_fc     = (const float*)d_in[12];
    float* out = (float*)d_out;

    cudaFuncSetAttribute(gates_kernel, cudaFuncAttributeMaxDynamicSharedMemorySize, GEMM_SMEM);
    cudaFuncSetAttribute(fc_kernel, cudaFuncAttributeMaxDynamicSharedMemorySize, GEMM_SMEM);

    attn_kernel<<<256, 256>>>(input, enc, hidden, emb, W_energy, b_energy);
    gates_kernel<<<dim3(32, 4), 512, GEMM_SMEM>>>(W_ih, W_hh);
    lstm_kernel<<<1024, 256>>>(cell, b_ih, b_hh, out);
    fc_kernel<<<250, 512, GEMM_SMEM>>>(W_fc, b_fc, out);
}